// round 1
// baseline (speedup 1.0000x reference)
#include <cuda_runtime.h>

#define D 128
#define MAXN 100096

// Per-node "has incoming edge" flags for the two edge types.
__device__ unsigned char g_ind0[MAXN];
__device__ unsigned char g_ind1[MAXN];

__global__ void zero_flags_kernel(int nwords) {
    int i = blockIdx.x * blockDim.x + threadIdx.x;
    if (i < nwords) {
        ((unsigned int*)g_ind0)[i] = 0u;
        ((unsigned int*)g_ind1)[i] = 0u;
    }
}

__global__ void mark_flags_kernel(const int* __restrict__ d0, int E0,
                                  const int* __restrict__ d1, int E1) {
    int i = blockIdx.x * blockDim.x + threadIdx.x;
    if (i < E0) {
        g_ind0[d0[i]] = 1;
    } else {
        i -= E0;
        if (i < E1) g_ind1[d1[i]] = 1;
    }
}

// Fused: v = feat@Wr^T + br ; per-head dots vs rel_attn_{l,r} ; softmax over
// heads for each of 3 relations ; out = relu((b0*ind0+b1*ind1)*v + b2*feat).
//
// Block: 256 threads. tid&127 = output element t (head = t>>5), tid>>7 = node
// sub-lane. Each iteration handles 8 nodes (4 per sub-lane for FFMA ILP).
// Wr lives in smem with 132-float row pitch (conflict-free float4 reads).
__global__ void __launch_bounds__(256, 2) fused_kernel(
    const float* __restrict__ feat, const float* __restrict__ Wr,
    const float* __restrict__ br, const float* __restrict__ rl,
    const float* __restrict__ rr, float* __restrict__ out, int N)
{
    extern __shared__ float smem[];
    float* Wr_s   = smem;               // 128*132 = 16896
    float* feat_s = Wr_s + 128 * 132;   // 8*128   = 1024
    float* rr_s   = feat_s + 1024;      // 128
    float* rl_s   = rr_s + 128;         // 128
    float* br_s   = rl_s + 128;         // 128
    float* red_s  = br_s + 128;         // 8 nodes * 4 heads * 4 = 128
    float* beta_s = red_s + 128;        // 8 nodes * 3 rel * 4 heads = 96
    float* flag_s = beta_s + 96;        // 16

    const int tid  = threadIdx.x;
    const int t    = tid & 127;
    const int ln   = tid >> 7;          // node sub-lane (0/1)
    const int head = (tid >> 5) & 3;
    const int lid  = tid & 31;

    // Stage Wr (padded rows) + small vectors once per block.
    for (int idx = tid; idx < 128 * 128; idx += 256) {
        int r = idx >> 7, c = idx & 127;
        Wr_s[r * 132 + c] = Wr[idx];
    }
    if (tid < 128) {
        rr_s[tid] = rr[tid];
        rl_s[tid] = rl[tid];
        br_s[tid] = br[tid];
    }
    __syncthreads();

    const int ngroups = (N + 7) >> 3;
    for (int g = blockIdx.x; g < ngroups; g += gridDim.x) {
        const int base = g << 3;

        // Stage 8 feat rows (coalesced float4: warp w loads node w's row).
        {
            int node = tid >> 5;
            int n = base + node;
            float4 v4 = make_float4(0.f, 0.f, 0.f, 0.f);
            if (n < N) v4 = ((const float4*)feat)[n * 32 + lid];
            ((float4*)feat_s)[node * 32 + lid] = v4;
        }
        if (tid < 16) {
            int m = tid & 7;
            int n = base + m;
            float f = 0.f;
            if (n < N) f = (tid < 8) ? (float)g_ind0[n] : (float)g_ind1[n];
            flag_s[tid] = f;
        }
        __syncthreads();

        // v[t] = sum_i Wr[t][i] * feat[n][i] + br[t], for 4 nodes per thread.
        float acc[4];
        {
            float bt = br_s[t];
            acc[0] = bt; acc[1] = bt; acc[2] = bt; acc[3] = bt;
        }
        {
            const float4* w4 = (const float4*)&Wr_s[t * 132];
            const float4* fb = (const float4*)&feat_s[ln * 512];
            #pragma unroll 4
            for (int i = 0; i < 32; i++) {
                float4 w = w4[i];
                #pragma unroll
                for (int mm = 0; mm < 4; mm++) {
                    float4 f = fb[mm * 32 + i];
                    acc[mm] = fmaf(w.x, f.x, acc[mm]);
                    acc[mm] = fmaf(w.y, f.y, acc[mm]);
                    acc[mm] = fmaf(w.z, f.z, acc[mm]);
                    acc[mm] = fmaf(w.w, f.w, acc[mm]);
                }
            }
        }

        // Per-head dot products: sv = <v, rr>, sf = <feat, rr>, al = <feat, rl>
        {
            float rrt = rr_s[t];
            float rlt = rl_s[t];
            #pragma unroll
            for (int mm = 0; mm < 4; mm++) {
                int m = ln * 4 + mm;
                float fv = feat_s[m * 128 + t];
                float pv = acc[mm] * rrt;
                float pf = fv * rrt;
                float pl = fv * rlt;
                #pragma unroll
                for (int o = 16; o; o >>= 1) {
                    pv += __shfl_xor_sync(0xffffffffu, pv, o);
                    pf += __shfl_xor_sync(0xffffffffu, pf, o);
                    pl += __shfl_xor_sync(0xffffffffu, pl, o);
                }
                if (lid == 0) {
                    float* r = &red_s[(m * 4 + head) * 4];
                    r[0] = pv; r[1] = pf; r[2] = pl;
                }
            }
        }
        __syncthreads();

        // Beta: softmax over the 4 heads, for each (node m, relation j).
        if (tid < 24) {
            int m = tid / 3, j = tid % 3;
            float i0 = flag_s[m], i1 = flag_s[8 + m];
            float L[4];
            #pragma unroll
            for (int h = 0; h < 4; h++) {
                const float* r = &red_s[(m * 4 + h) * 4];
                float sv = r[0], sf = r[1], al = r[2];
                float ar = (j == 0) ? i0 * sv : (j == 1) ? i1 * sv : sf;
                float x = al + ar;
                L[h] = (x > 0.f) ? x : 0.2f * x;   // leaky_relu(.,0.2)
            }
            float mx = fmaxf(fmaxf(L[0], L[1]), fmaxf(L[2], L[3]));
            float e0 = __expf(L[0] - mx), e1 = __expf(L[1] - mx);
            float e2 = __expf(L[2] - mx), e3 = __expf(L[3] - mx);
            float inv = 1.f / (e0 + e1 + e2 + e3);
            float* b = &beta_s[(m * 3 + j) * 4];
            b[0] = e0 * inv; b[1] = e1 * inv; b[2] = e2 * inv; b[3] = e3 * inv;
        }
        __syncthreads();

        // Epilogue: out = relu((b0*ind0 + b1*ind1)*v + b2*feat)
        #pragma unroll
        for (int mm = 0; mm < 4; mm++) {
            int m = ln * 4 + mm;
            int n = base + m;
            if (n < N) {
                float i0  = flag_s[m], i1 = flag_s[8 + m];
                float g01 = beta_s[(m * 3 + 0) * 4 + head] * i0
                          + beta_s[(m * 3 + 1) * 4 + head] * i1;
                float b2  = beta_s[(m * 3 + 2) * 4 + head];
                float fv  = feat_s[m * 128 + t];
                float o   = g01 * acc[mm] + b2 * fv;
                out[n * 128 + t] = fmaxf(o, 0.f);
            }
        }
        __syncthreads();  // protect feat_s/red_s/beta_s before next group
    }
}

extern "C" void kernel_launch(void* const* d_in, const int* in_sizes, int n_in,
                              void* d_out, int out_size) {
    // Input order: feat, Wl, bl, Wr, br, attn_l, attn_r, rel_attn_l,
    //              rel_attn_r, alpha, src0, dst0, src1, dst1
    const float* feat = (const float*)d_in[0];
    const float* Wr   = (const float*)d_in[3];
    const float* br   = (const float*)d_in[4];
    const float* rl   = (const float*)d_in[7];
    const float* rr   = (const float*)d_in[8];
    const int* dst0   = (const int*)d_in[11];
    const int* dst1   = (const int*)d_in[13];
    float* out        = (float*)d_out;

    const int N  = in_sizes[0] / D;
    const int E0 = in_sizes[11];
    const int E1 = in_sizes[13];

    // 1) Flags from dst0/dst1 (k/att/softmax collapse: only edge existence matters).
    {
        int nwords = (N + 3) / 4;
        zero_flags_kernel<<<(nwords + 255) / 256, 256>>>(nwords);
        int tot = E0 + E1;
        mark_flags_kernel<<<(tot + 255) / 256, 256>>>(dst0, E0, dst1, E1);
    }

    // 2) Fused GEMM + beta-softmax + epilogue.
    {
        static const int SMEM_BYTES = (128 * 132 + 1024 + 3 * 128 + 128 + 96 + 16) * 4;
        cudaFuncSetAttribute(fused_kernel,
                             cudaFuncAttributeMaxDynamicSharedMemorySize,
                             SMEM_BYTES);
        int nsm = 148;
        cudaDeviceGetAttribute(&nsm, cudaDevAttrMultiProcessorCount, 0);
        int grid = 2 * nsm;
        int ngroups = (N + 7) >> 3;
        if (grid > ngroups) grid = ngroups;
        fused_kernel<<<grid, 256, SMEM_BYTES>>>(feat, Wr, br, rl, rr, out, N);
    }
}

// round 2
// speedup vs baseline: 2.2468x; 2.2468x over previous
#include <cuda_runtime.h>
#include <cuda_bf16.h>

#define MAXN 100096

// Per-node "has incoming edge" flags for the two edge types.
__device__ unsigned char g_ind0[MAXN];
__device__ unsigned char g_ind1[MAXN];

__global__ void zero_flags_kernel(int nwords) {
    int i = blockIdx.x * blockDim.x + threadIdx.x;
    if (i < nwords) {
        ((unsigned int*)g_ind0)[i] = 0u;
        ((unsigned int*)g_ind1)[i] = 0u;
    }
}

__global__ void mark_flags_kernel(const int* __restrict__ d0, int E0,
                                  const int* __restrict__ d1, int E1) {
    int i = blockIdx.x * blockDim.x + threadIdx.x;
    if (i < E0) {
        g_ind0[d0[i]] = 1;
    } else {
        i -= E0;
        if (i < E1) g_ind1[d1[i]] = 1;
    }
}

__device__ __forceinline__ void mma16816(float* c, const unsigned* a, const unsigned* b) {
    asm volatile(
        "mma.sync.aligned.m16n8k16.row.col.f32.bf16.bf16.f32 "
        "{%0,%1,%2,%3},{%4,%5,%6,%7},{%8,%9},{%0,%1,%2,%3};\n"
        : "+f"(c[0]), "+f"(c[1]), "+f"(c[2]), "+f"(c[3])
        : "r"(a[0]), "r"(a[1]), "r"(a[2]), "r"(a[3]), "r"(b[0]), "r"(b[1]));
}

__device__ __forceinline__ unsigned pack_bf16x2(float f0, float f1) {
    unsigned u0 = (unsigned)__bfloat16_as_ushort(__float2bfloat16(f0));
    unsigned u1 = (unsigned)__bfloat16_as_ushort(__float2bfloat16(f1));
    return u0 | (u1 << 16);
}
__device__ __forceinline__ float bf_lo(unsigned u) {
    return __bfloat162float(__ushort_as_bfloat16((unsigned short)(u & 0xffffu)));
}
__device__ __forceinline__ float bf_hi(unsigned u) {
    return __bfloat162float(__ushort_as_bfloat16((unsigned short)(u >> 16)));
}

// smem layout (u32 units)
#define STG_OFF   0            // 16384 : fp32 staging (Wr in prologue, feat tiles after)
#define AHI_OFF   16384        // 8192  : A hi fragments (128 nodes x 128 k, bf16x2)
#define ALO_OFF   (AHI_OFF + 8192)
#define BHI_OFF   (ALO_OFF + 8192)   // 9216 : B-ext hi fragments (144 cols x 128 k)
#define BLO_OFF   (BHI_OFF + 9216)
#define RED_OFF   (BLO_OFF + 9216)   // 1536 floats : per-node sv/sf/al (pitch 12)
#define GBUF_OFF  (RED_OFF + 1536)   // 1152 floats : per-node g01[4],b2[4] (pitch 9)
#define RRS_OFF   (GBUF_OFF + 1152)  // 128
#define RLS_OFF   (RRS_OFF + 128)
#define BRS_OFF   (RLS_OFF + 128)
#define QS_OFF    (BRS_OFF + 128)    // 512
#define CHS_OFF   (QS_OFF + 512)     // 8
#define SMEM_U32  (CHS_OFF + 8)

__device__ __forceinline__ void issue_tile_loads(unsigned* STG, const float* feat,
                                                 int tile, int N, int tid) {
    #pragma unroll
    for (int it = 0; it < 16; it++) {
        int idx4 = tid + it * 256;
        int n = idx4 >> 5, c4 = idx4 & 31;
        int node = tile * 128 + n;
        if (node > N - 1) node = N - 1;   // clamp: duplicated rows, stores are guarded
        const float4* src = ((const float4*)feat) + (size_t)node * 32 + c4;
        unsigned dst = (unsigned)__cvta_generic_to_shared(&STG[idx4 * 4]);
        asm volatile("cp.async.cg.shared.global [%0],[%1],16;" :: "r"(dst), "l"(src));
    }
}

// v = feat @ Wr^T (+br), with 16 extra B columns computing sv/sf/al per head
// (all linear in feat: sv = feat.q_h + c_h). bf16 hi/lo 3-term MMA for fp32-like
// accuracy. Epilogue: beta softmax over heads, out = relu(g01*v + b2*feat).
__global__ void __launch_bounds__(256) fused_kernel(
    const float* __restrict__ feat, const float* __restrict__ Wr,
    const float* __restrict__ br, const float* __restrict__ rl,
    const float* __restrict__ rr, float* __restrict__ out, int N)
{
    extern __shared__ unsigned smem_u[];
    unsigned* STG = smem_u + STG_OFF;
    unsigned* AHI = smem_u + AHI_OFF;
    unsigned* ALO = smem_u + ALO_OFF;
    unsigned* BHI = smem_u + BHI_OFF;
    unsigned* BLO = smem_u + BLO_OFF;
    float* red  = (float*)(smem_u + RED_OFF);
    float* gbuf = (float*)(smem_u + GBUF_OFF);
    float* rr_s = (float*)(smem_u + RRS_OFF);
    float* rl_s = (float*)(smem_u + RLS_OFF);
    float* br_s = (float*)(smem_u + BRS_OFF);
    float* q_s  = (float*)(smem_u + QS_OFF);
    float* ch_s = (float*)(smem_u + CHS_OFF);

    const int tid = threadIdx.x;
    const int lane = tid & 31;
    const int warp = tid >> 5;
    const int wg = warp >> 2;       // 0: n-tiles 0-8, 1: n-tiles 9-17
    const int mp = warp & 3;        // m-tile pair {2mp, 2mp+1}

    // ---- prologue: stage Wr fp32, compute q_h and c_h, build B-ext fragments
    if (tid < 128) { rr_s[tid] = rr[tid]; rl_s[tid] = rl[tid]; br_s[tid] = br[tid]; }
    for (int i = tid; i < 4096; i += 256)
        ((float4*)STG)[i] = ((const float4*)Wr)[i];
    __syncthreads();

    const float* WrS = (const float*)STG;
    for (int p = tid; p < 512; p += 256) {
        int h = p >> 7, k = p & 127;
        float s = 0.f;
        #pragma unroll 4
        for (int t = 0; t < 32; t++)
            s += WrS[(h * 32 + t) * 128 + k] * rr_s[h * 32 + t];
        q_s[p] = s;
    }
    if (tid < 4) {
        float s = 0.f;
        for (int t = 0; t < 32; t++) s += br_s[tid * 32 + t] * rr_s[tid * 32 + t];
        ch_s[tid] = s;
    }
    __syncthreads();

    // B-ext[k][t']: t'<128: Wr[t'][k]; 128-131: q_h[k]; 132-135: rr masked by head;
    // 136-139: rl masked; 140-143: 0.  Stored directly in mma fragment layout.
    for (int i = tid; i < 9216; i += 256) {
        int j  = i & 1;
        int ln = (i >> 1) & 31;
        int kc = (i >> 6) & 7;
        int nt = i >> 9;
        int tp = nt * 8 + (ln >> 2);
        int k0 = kc * 16 + (ln & 3) * 2 + j * 8;
        float f0, f1;
        {
            float v[2];
            #pragma unroll
            for (int e = 0; e < 2; e++) {
                int k = k0 + e;
                float x;
                if (tp < 128)      x = WrS[tp * 128 + k];
                else if (tp < 132) x = q_s[(tp - 128) * 128 + k];
                else if (tp < 136) x = ((k >> 5) == (tp - 132)) ? rr_s[k] : 0.f;
                else if (tp < 140) x = ((k >> 5) == (tp - 136)) ? rl_s[k] : 0.f;
                else               x = 0.f;
                v[e] = x;
            }
            f0 = v[0]; f1 = v[1];
        }
        __nv_bfloat16 h0 = __float2bfloat16(f0), h1 = __float2bfloat16(f1);
        float l0 = f0 - __bfloat162float(h0);
        float l1 = f1 - __bfloat162float(h1);
        BHI[i] = (unsigned)__bfloat16_as_ushort(h0) |
                 ((unsigned)__bfloat16_as_ushort(h1) << 16);
        BLO[i] = pack_bf16x2(l0, l1);
    }
    __syncthreads();   // STG free for feat staging now

    const int T = (N + 127) >> 7;
    int tile = blockIdx.x;
    if (tile < T) issue_tile_loads(STG, feat, tile, N, tid);
    asm volatile("cp.async.commit_group;");

    for (; tile < T; tile += gridDim.x) {
        asm volatile("cp.async.wait_group 0;");
        __syncthreads();   // staging ready; prev iter epilogue done

        // convert staging fp32 -> A hi/lo fragments (mma layout)
        #pragma unroll
        for (int it = 0; it < 16; it++) {
            int idx4 = tid + it * 256;
            int n = idx4 >> 5, c4 = idx4 & 31;
            float4 f = ((const float4*)STG)[idx4];
            int mt = n >> 4, r = n & 15;
            #pragma unroll
            for (int p = 0; p < 2; p++) {
                int kk = c4 * 2 + p;
                int kc = kk >> 3, kkr = kk & 7;
                int ln = (r & 7) * 4 + (kkr & 3);
                int j  = ((kkr >> 2) << 1) | (r >> 3);
                int di = ((mt * 8 + kc) * 32 + ln) * 4 + j;
                float a0 = p ? f.z : f.x;
                float a1 = p ? f.w : f.y;
                __nv_bfloat16 h0 = __float2bfloat16(a0), h1 = __float2bfloat16(a1);
                float l0 = a0 - __bfloat162float(h0);
                float l1 = a1 - __bfloat162float(h1);
                AHI[di] = (unsigned)__bfloat16_as_ushort(h0) |
                          ((unsigned)__bfloat16_as_ushort(h1) << 16);
                ALO[di] = pack_bf16x2(l0, l1);
            }
        }
        __syncthreads();

        // prefetch next tile (overlaps with MMA below)
        {
            int nxt = tile + gridDim.x;
            if (nxt < T) issue_tile_loads(STG, feat, nxt, N, tid);
            asm volatile("cp.async.commit_group;");
        }

        // ---- MMA: warp = 2 m-tiles x 9 n-tiles, K = 8 chunks, 3-term bf16 split
        float acc[2][9][4];
        #pragma unroll
        for (int a = 0; a < 2; a++)
            #pragma unroll
            for (int b = 0; b < 9; b++)
                #pragma unroll
                for (int c = 0; c < 4; c++) acc[a][b][c] = 0.f;

        const int mt0 = 2 * mp, mt1 = 2 * mp + 1;
        #pragma unroll 1
        for (int kc = 0; kc < 8; kc++) {
            uint4 ah0 = ((const uint4*)AHI)[(mt0 * 8 + kc) * 32 + lane];
            uint4 ah1 = ((const uint4*)AHI)[(mt1 * 8 + kc) * 32 + lane];
            uint4 aw0 = ((const uint4*)ALO)[(mt0 * 8 + kc) * 32 + lane];
            uint4 aw1 = ((const uint4*)ALO)[(mt1 * 8 + kc) * 32 + lane];
            #pragma unroll
            for (int nt9 = 0; nt9 < 9; nt9++) {
                int gnt = wg * 9 + nt9;
                uint2 bh = ((const uint2*)BHI)[(gnt * 8 + kc) * 32 + lane];
                uint2 bl = ((const uint2*)BLO)[(gnt * 8 + kc) * 32 + lane];
                mma16816(acc[0][nt9], (const unsigned*)&ah0, (const unsigned*)&bh);
                mma16816(acc[1][nt9], (const unsigned*)&ah1, (const unsigned*)&bh);
                mma16816(acc[0][nt9], (const unsigned*)&ah0, (const unsigned*)&bl);
                mma16816(acc[1][nt9], (const unsigned*)&ah1, (const unsigned*)&bl);
                mma16816(acc[0][nt9], (const unsigned*)&aw0, (const unsigned*)&bh);
                mma16816(acc[1][nt9], (const unsigned*)&aw1, (const unsigned*)&bh);
            }
        }

        // ---- extract sv/sf/al (cols 128..139 live in n-tiles 16,17 -> wg==1)
        if (wg == 1) {
            int cidx = (lane & 3) * 2;
            #pragma unroll
            for (int mtl = 0; mtl < 2; mtl++) {
                int mt = 2 * mp + mtl;
                #pragma unroll
                for (int j0 = 0; j0 < 2; j0++) {
                    int nodeL = mt * 16 + (lane >> 2) + 8 * j0;
                    float s0 = acc[mtl][7][2 * j0];
                    float s1 = acc[mtl][7][2 * j0 + 1];
                    if (cidx < 4) { s0 += ch_s[cidx]; s1 += ch_s[cidx + 1]; }
                    red[nodeL * 12 + cidx]     = s0;
                    red[nodeL * 12 + cidx + 1] = s1;
                    if (cidx < 4) {
                        red[nodeL * 12 + 8 + cidx]     = acc[mtl][8][2 * j0];
                        red[nodeL * 12 + 8 + cidx + 1] = acc[mtl][8][2 * j0 + 1];
                    }
                }
            }
        }
        __syncthreads();

        // ---- beta softmax over heads, fold flags into g01/b2
        if (tid < 128) {
            int ng = tile * 128 + tid;
            int cn = ng < N ? ng : N - 1;
            float i0 = (float)g_ind0[cn];
            float i1 = (float)g_ind1[cn];
            const float* r = &red[tid * 12];
            float sv0 = r[0], sv1 = r[1], sv2 = r[2], sv3 = r[3];
            float sf0 = r[4], sf1 = r[5], sf2 = r[6], sf3 = r[7];
            float al0 = r[8], al1 = r[9], al2 = r[10], al3 = r[11];
            float bta[3][4];
            #pragma unroll
            for (int jr = 0; jr < 3; jr++) {
                float a0 = (jr == 0) ? i0 * sv0 : (jr == 1) ? i1 * sv0 : sf0;
                float a1 = (jr == 0) ? i0 * sv1 : (jr == 1) ? i1 * sv1 : sf1;
                float a2 = (jr == 0) ? i0 * sv2 : (jr == 1) ? i1 * sv2 : sf2;
                float a3 = (jr == 0) ? i0 * sv3 : (jr == 1) ? i1 * sv3 : sf3;
                float x0 = al0 + a0, x1 = al1 + a1, x2 = al2 + a2, x3 = al3 + a3;
                x0 = (x0 > 0.f) ? x0 : 0.2f * x0;
                x1 = (x1 > 0.f) ? x1 : 0.2f * x1;
                x2 = (x2 > 0.f) ? x2 : 0.2f * x2;
                x3 = (x3 > 0.f) ? x3 : 0.2f * x3;
                float mx = fmaxf(fmaxf(x0, x1), fmaxf(x2, x3));
                float e0 = __expf(x0 - mx), e1 = __expf(x1 - mx);
                float e2 = __expf(x2 - mx), e3 = __expf(x3 - mx);
                float inv = 1.f / (e0 + e1 + e2 + e3);
                bta[jr][0] = e0 * inv; bta[jr][1] = e1 * inv;
                bta[jr][2] = e2 * inv; bta[jr][3] = e3 * inv;
            }
            #pragma unroll
            for (int h = 0; h < 4; h++) {
                gbuf[tid * 9 + h]     = bta[0][h] * i0 + bta[1][h] * i1;
                gbuf[tid * 9 + 4 + h] = bta[2][h];
            }
        }
        __syncthreads();

        // ---- final: out = relu(g01*(v+br) + b2*feat), feat from hi+lo frags
        {
            const int ntmax = (wg == 0) ? 9 : 7;   // output cols 0..127 only
            #pragma unroll
            for (int mtl = 0; mtl < 2; mtl++) {
                int mt = 2 * mp + mtl;
                #pragma unroll
                for (int nt9 = 0; nt9 < 9; nt9++) {
                    if (nt9 >= ntmax) break;
                    int gnt = wg * 9 + nt9;
                    int kc = gnt >> 1, j1 = gnt & 1;
                    int head = gnt >> 2;
                    int tcol = gnt * 8 + (lane & 3) * 2;
                    float2 brv = *(const float2*)&br_s[tcol];
                    #pragma unroll
                    for (int j0 = 0; j0 < 2; j0++) {
                        int nodeL = mt * 16 + (lane >> 2) + 8 * j0;
                        int ng = tile * 128 + nodeL;
                        if (ng < N) {
                            float g01 = gbuf[nodeL * 9 + head];
                            float b2v = gbuf[nodeL * 9 + 4 + head];
                            int fidx = ((mt * 8 + kc) * 32 + lane) * 4 + (j0 + 2 * j1);
                            unsigned fh = AHI[fidx], fl = ALO[fidx];
                            float f0 = bf_lo(fh) + bf_lo(fl);
                            float f1 = bf_hi(fh) + bf_hi(fl);
                            float v0 = acc[mtl][nt9][2 * j0]     + brv.x;
                            float v1 = acc[mtl][nt9][2 * j0 + 1] + brv.y;
                            float o0 = fmaxf(fmaf(g01, v0, b2v * f0), 0.f);
                            float o1 = fmaxf(fmaf(g01, v1, b2v * f1), 0.f);
                            *(float2*)&out[(size_t)ng * 128 + tcol] = make_float2(o0, o1);
                        }
                    }
                }
            }
        }
        // next-iteration top-of-loop sync protects A frags / red / gbuf
    }
}

extern "C" void kernel_launch(void* const* d_in, const int* in_sizes, int n_in,
                              void* d_out, int out_size) {
    // Inputs: feat, Wl, bl, Wr, br, attn_l, attn_r, rel_attn_l, rel_attn_r,
    //         alpha, src0, dst0, src1, dst1
    const float* feat = (const float*)d_in[0];
    const float* Wr   = (const float*)d_in[3];
    const float* br   = (const float*)d_in[4];
    const float* rl   = (const float*)d_in[7];
    const float* rr   = (const float*)d_in[8];
    const int* dst0   = (const int*)d_in[11];
    const int* dst1   = (const int*)d_in[13];
    float* out        = (float*)d_out;

    const int N  = in_sizes[0] / 128;
    const int E0 = in_sizes[11];
    const int E1 = in_sizes[13];

    {
        int nwords = (N + 3) / 4;
        zero_flags_kernel<<<(nwords + 255) / 256, 256>>>(nwords);
        int tot = E0 + E1;
        mark_flags_kernel<<<(tot + 255) / 256, 256>>>(dst0, E0, dst1, E1);
    }

    {
        const int SMEM_BYTES = SMEM_U32 * 4;
        cudaFuncSetAttribute(fused_kernel,
                             cudaFuncAttributeMaxDynamicSharedMemorySize,
                             SMEM_BYTES);
        int nsm = 148;
        cudaDeviceGetAttribute(&nsm, cudaDevAttrMultiProcessorCount, 0);
        int T = (N + 127) >> 7;
        int grid = nsm < T ? nsm : T;
        fused_kernel<<<grid, 256, SMEM_BYTES>>>(feat, Wr, br, rl, rr, out, N);
    }
}

// round 4
// speedup vs baseline: 2.3297x; 1.0369x over previous
#include <cuda_runtime.h>
#include <cuda_bf16.h>
#include <cstdint>

#define MAXN 100096

__device__ unsigned char g_ind0[MAXN];
__device__ unsigned char g_ind1[MAXN];
__device__ volatile unsigned int g_bar;

__device__ __forceinline__ void mma16816(float* c, const unsigned* a, const unsigned* b) {
    asm volatile(
        "mma.sync.aligned.m16n8k16.row.col.f32.bf16.bf16.f32 "
        "{%0,%1,%2,%3},{%4,%5,%6,%7},{%8,%9},{%0,%1,%2,%3};\n"
        : "+f"(c[0]), "+f"(c[1]), "+f"(c[2]), "+f"(c[3])
        : "r"(a[0]), "r"(a[1]), "r"(a[2]), "r"(a[3]), "r"(b[0]), "r"(b[1]));
}

__device__ __forceinline__ float bfl(unsigned u) {
    return __bfloat162float(__ushort_as_bfloat16((unsigned short)(u & 0xffffu)));
}
__device__ __forceinline__ float bfh(unsigned u) {
    return __bfloat162float(__ushort_as_bfloat16((unsigned short)(u >> 16)));
}

// Software grid barrier: valid because grid <= #SMs and occupancy is 1 block/SM
// (all blocks co-resident). Monotonic counter survives graph replays.
__device__ __forceinline__ void grid_bar(unsigned nb) {
    __syncthreads();
    if (threadIdx.x == 0) {
        __threadfence();
        unsigned old = atomicAdd((unsigned*)&g_bar, 1u);
        unsigned target = (old / nb + 1u) * nb;
        while (g_bar < target) { }
        __threadfence();
    }
    __syncthreads();
}

// smem layout (u32 units)
#define STG_OFF   0            // 16384 : fp32 feat staging (also Wr-free; B built from gmem)
#define AHI_OFF   16384        // 8192  : A hi fragments (128 nodes x 128 k, bf16x2)
#define ALO_OFF   24576        // 8192
#define BHI_OFF   32768        // 9216  : B-ext hi fragments (144 cols x 128 k)
#define BLO_OFF   41984        // 9216
#define RED_OFF   51200        // 1536 floats : per-node sv/sf/al (pitch 12)
#define GBUF_OFF  52736        // 1152 floats : per-node g01[4],b2[4] (pitch 9)
#define BRS_OFF   53888        // 128
#define QS_OFF    54016        // 512
#define CHS_OFF   54528        // 8
#define SMEM_U32  54536        // 218144 bytes

__device__ __forceinline__ void prefetch_tile(unsigned* STG, const float* feat,
                                              long tile, int N, int tid, int nthr) {
    #pragma unroll
    for (int it = 0; it < 8; it++) {
        int idx4 = tid + it * nthr;
        long node = tile * 128 + (idx4 >> 5);
        if (node > N - 1) node = N - 1;
        const float4* src = ((const float4*)feat) + node * 32 + (idx4 & 31);
        unsigned dst = (unsigned)__cvta_generic_to_shared(&STG[idx4 * 4]);
        asm volatile("cp.async.cg.shared.global [%0],[%1],16;" :: "r"(dst), "l"(src));
    }
}

// fp32 staging -> bf16 hi/lo split -> mma-fragment-layout stores
__device__ __forceinline__ void convert_tile(const unsigned* STG, int tid, int nthr,
                                             unsigned* AHI, unsigned* ALO) {
    #pragma unroll
    for (int it = 0; it < 8; it++) {
        int idx4 = tid + it * nthr;
        int n = idx4 >> 5, c4 = idx4 & 31;
        float4 f = ((const float4*)STG)[idx4];
        int mt = n >> 4, r = n & 15;
        #pragma unroll
        for (int p = 0; p < 2; p++) {
            int kk = c4 * 2 + p;
            int kc = kk >> 3, kkr = kk & 7;
            int ln = (r & 7) * 4 + (kkr & 3);
            int j  = ((kkr >> 2) << 1) | (r >> 3);
            int di = ((mt * 8 + kc) * 32 + ln) * 4 + j;
            float a0 = p ? f.z : f.x;
            float a1 = p ? f.w : f.y;
            unsigned u0 = __float_as_uint(a0) + 0x8000u;
            unsigned u1 = __float_as_uint(a1) + 0x8000u;
            unsigned hi;
            asm("prmt.b32 %0,%1,%2,0x7632;" : "=r"(hi) : "r"(u0), "r"(u1));
            float l0 = a0 - __uint_as_float(u0 & 0xffff0000u);
            float l1 = a1 - __uint_as_float(u1 & 0xffff0000u);
            unsigned lo;
            asm("cvt.rn.bf16x2.f32 %0, %1, %2;" : "=r"(lo) : "f"(l1), "f"(l0));
            AHI[di] = hi;
            ALO[di] = lo;
        }
    }
}

template<int BASE, int CNT>
__device__ __forceinline__ void mma_phase(float (&acc)[2][5][4],
    const unsigned* AHI, const unsigned* ALO,
    const unsigned* BHI, const unsigned* BLO, int lane, int mp)
{
    const int mt0 = 2 * mp, mt1 = 2 * mp + 1;
    #pragma unroll 1
    for (int kc = 0; kc < 8; kc++) {
        uint4 ah0 = ((const uint4*)AHI)[(mt0 * 8 + kc) * 32 + lane];
        uint4 ah1 = ((const uint4*)AHI)[(mt1 * 8 + kc) * 32 + lane];
        uint4 al0 = ((const uint4*)ALO)[(mt0 * 8 + kc) * 32 + lane];
        uint4 al1 = ((const uint4*)ALO)[(mt1 * 8 + kc) * 32 + lane];
        #pragma unroll
        for (int i = 0; i < CNT; i++) {
            int gnt = BASE + i;
            uint2 bh = ((const uint2*)BHI)[(gnt * 8 + kc) * 32 + lane];
            uint2 bl = ((const uint2*)BLO)[(gnt * 8 + kc) * 32 + lane];
            mma16816(acc[0][i], (const unsigned*)&ah0, (const unsigned*)&bh);
            mma16816(acc[1][i], (const unsigned*)&ah1, (const unsigned*)&bh);
            mma16816(acc[0][i], (const unsigned*)&ah0, (const unsigned*)&bl);
            mma16816(acc[1][i], (const unsigned*)&ah1, (const unsigned*)&bl);
            mma16816(acc[0][i], (const unsigned*)&al0, (const unsigned*)&bh);
            mma16816(acc[1][i], (const unsigned*)&al1, (const unsigned*)&bh);
        }
    }
}

template<int BASE, int CNT>
__device__ __forceinline__ void final_phase(const float (&acc)[2][5][4],
    const unsigned* AHI, const unsigned* ALO, const float* gbuf,
    const float* br_s, float* out, long tile, int N, int lane, int mp)
{
    #pragma unroll
    for (int mtl = 0; mtl < 2; mtl++) {
        int mt = 2 * mp + mtl;
        #pragma unroll
        for (int i = 0; i < CNT; i++) {
            int gnt = BASE + i;
            if (gnt >= 16) break;           // output cols 0..127 only
            int kc = gnt >> 1, j1 = gnt & 1;
            int head = gnt >> 2;
            int tcol = gnt * 8 + (lane & 3) * 2;
            float2 brv = *(const float2*)&br_s[tcol];
            #pragma unroll
            for (int j0 = 0; j0 < 2; j0++) {
                int nodeL = mt * 16 + (lane >> 2) + 8 * j0;
                long ng = tile * 128 + nodeL;
                if (ng < N) {
                    float g01 = gbuf[nodeL * 9 + head];
                    float b2v = gbuf[nodeL * 9 + 4 + head];
                    int fidx = ((mt * 8 + kc) * 32 + lane) * 4 + (j0 + 2 * j1);
                    unsigned fh = AHI[fidx], fl = ALO[fidx];
                    float f0 = bfl(fh) + bfl(fl);
                    float f1 = bfh(fh) + bfh(fl);
                    float v0 = acc[mtl][i][2 * j0]     + brv.x;
                    float v1 = acc[mtl][i][2 * j0 + 1] + brv.y;
                    float o0 = fmaxf(fmaf(g01, v0, b2v * f0), 0.f);
                    float o1 = fmaxf(fmaf(g01, v1, b2v * f1), 0.f);
                    *(float2*)&out[ng * 128 + tcol] = make_float2(o0, o1);
                }
            }
        }
    }
}

// One persistent kernel: flags (zero, barrier, mark, barrier) then the fused
// GEMM+softmax+epilogue loop over node tiles.
__global__ void __launch_bounds__(512, 1) fused_kernel(
    const float* __restrict__ feat, const float* __restrict__ Wr,
    const float* __restrict__ br, const float* __restrict__ rl,
    const float* __restrict__ rr,
    const int* __restrict__ d0, int E0, const int* __restrict__ d1, int E1,
    float* __restrict__ out, int N)
{
    extern __shared__ unsigned smem_u[];
    unsigned* STG = smem_u + STG_OFF;
    unsigned* AHI = smem_u + AHI_OFF;
    unsigned* ALO = smem_u + ALO_OFF;
    unsigned* BHI = smem_u + BHI_OFF;
    unsigned* BLO = smem_u + BLO_OFF;
    float* red  = (float*)(smem_u + RED_OFF);
    float* gbuf = (float*)(smem_u + GBUF_OFF);
    float* br_s = (float*)(smem_u + BRS_OFF);
    float* q_s  = (float*)(smem_u + QS_OFF);
    float* ch_s = (float*)(smem_u + CHS_OFF);

    const int tid  = threadIdx.x;
    const int lane = tid & 31;
    const int warp = tid >> 5;
    const int mp = warp & 3;     // m-tile pair {2mp, 2mp+1}
    const int wg = warp >> 2;    // n-tile group
    const unsigned nb = gridDim.x;
    const int nthr = 512;

    // ---- phase 0: zero flags
    for (int i = blockIdx.x * nthr + tid; i < MAXN / 4; i += nb * nthr) {
        ((unsigned*)g_ind0)[i] = 0u;
        ((unsigned*)g_ind1)[i] = 0u;
    }
    grid_bar(nb);

    // ---- phase 1: mark flags
    for (int i = blockIdx.x * nthr + tid; i < E0 + E1; i += nb * nthr) {
        if (i < E0) g_ind0[d0[i]] = 1;
        else        g_ind1[d1[i - E0]] = 1;
    }

    // ---- prologue (overlaps other blocks' marking; barrier below)
    if (tid < 128) br_s[tid] = br[tid];
    __syncthreads();
    for (int p = tid; p < 512; p += nthr) {
        int h = p >> 7, k = p & 127;
        float s = 0.f;
        #pragma unroll 4
        for (int t = 0; t < 32; t++)
            s += __ldg(&Wr[(h * 32 + t) * 128 + k]) * __ldg(&rr[h * 32 + t]);
        q_s[p] = s;
    }
    if (tid < 4) {
        float s = 0.f;
        for (int t = 0; t < 32; t++)
            s += __ldg(&br[tid * 32 + t]) * __ldg(&rr[tid * 32 + t]);
        ch_s[tid] = s;
    }
    __syncthreads();

    // B-ext fragments: t'<128 Wr; 128-131 q_h; 132-135 rr masked; 136-139 rl
    // masked; 140-143 zero. Stored directly in mma fragment layout.
    for (int i = tid; i < 9216; i += nthr) {
        int j  = i & 1;
        int ln = (i >> 1) & 31;
        int kc = (i >> 6) & 7;
        int nt = i >> 9;
        int tp = nt * 8 + (ln >> 2);
        int k0 = kc * 16 + (ln & 3) * 2 + j * 8;
        float v[2];
        #pragma unroll
        for (int e = 0; e < 2; e++) {
            int k = k0 + e;
            float x;
            if (tp < 128)      x = __ldg(&Wr[tp * 128 + k]);
            else if (tp < 132) x = q_s[(tp - 128) * 128 + k];
            else if (tp < 136) x = ((k >> 5) == (tp - 132)) ? __ldg(&rr[k]) : 0.f;
            else if (tp < 140) x = ((k >> 5) == (tp - 136)) ? __ldg(&rl[k]) : 0.f;
            else               x = 0.f;
            v[e] = x;
        }
        unsigned u0 = __float_as_uint(v[0]) + 0x8000u;
        unsigned u1 = __float_as_uint(v[1]) + 0x8000u;
        unsigned hi;
        asm("prmt.b32 %0,%1,%2,0x7632;" : "=r"(hi) : "r"(u0), "r"(u1));
        float l0 = v[0] - __uint_as_float(u0 & 0xffff0000u);
        float l1 = v[1] - __uint_as_float(u1 & 0xffff0000u);
        unsigned lo;
        asm("cvt.rn.bf16x2.f32 %0, %1, %2;" : "=r"(lo) : "f"(l1), "f"(l0));
        BHI[i] = hi;
        BLO[i] = lo;
    }

    grid_bar(nb);   // marking complete everywhere; prologue smem visible

    // ---- main loop over node tiles
    const int T = (N + 127) >> 7;
    long tile0 = blockIdx.x;
    if (tile0 < T) prefetch_tile(STG, feat, tile0, N, tid, nthr);
    asm volatile("cp.async.commit_group;");

    for (long tile = tile0; tile < T; tile += nb) {
        asm volatile("cp.async.wait_group 0;");
        __syncthreads();   // STG ready; prev-iter final done with frags

        convert_tile(STG, tid, nthr, AHI, ALO);
        __syncthreads();   // frags ready; STG fully consumed

        long nxt = tile + nb;
        if (nxt < T) prefetch_tile(STG, feat, nxt, N, tid, nthr);
        asm volatile("cp.async.commit_group;");

        // ---- MMA (3-term bf16 split), warp = 2 m-tiles x 4-5 n-tiles
        float acc[2][5][4];
        #pragma unroll
        for (int a = 0; a < 2; a++)
            #pragma unroll
            for (int b = 0; b < 5; b++)
                #pragma unroll
                for (int c = 0; c < 4; c++) acc[a][b][c] = 0.f;

        switch (wg) {
            case 0: mma_phase<0, 5>(acc, AHI, ALO, BHI, BLO, lane, mp); break;
            case 1: mma_phase<5, 5>(acc, AHI, ALO, BHI, BLO, lane, mp); break;
            case 2: mma_phase<10, 4>(acc, AHI, ALO, BHI, BLO, lane, mp); break;
            default: mma_phase<14, 4>(acc, AHI, ALO, BHI, BLO, lane, mp); break;
        }

        // ---- extras (n-tiles 16,17 -> wg==3: i=2 sv/sf, i=3 al)
        if (wg == 3) {
            int cidx = (lane & 3) * 2;
            #pragma unroll
            for (int mtl = 0; mtl < 2; mtl++) {
                int mt = 2 * mp + mtl;
                #pragma unroll
                for (int j0 = 0; j0 < 2; j0++) {
                    int nl = mt * 16 + (lane >> 2) + 8 * j0;
                    float s0 = acc[mtl][2][2 * j0];
                    float s1 = acc[mtl][2][2 * j0 + 1];
                    if (cidx < 4) { s0 += ch_s[cidx]; s1 += ch_s[cidx + 1]; }
                    red[nl * 12 + cidx]     = s0;
                    red[nl * 12 + cidx + 1] = s1;
                    if (cidx < 4) {
                        red[nl * 12 + 8 + cidx]     = acc[mtl][3][2 * j0];
                        red[nl * 12 + 8 + cidx + 1] = acc[mtl][3][2 * j0 + 1];
                    }
                }
            }
        }
        __syncthreads();

        // ---- beta softmax over heads; fold flags into g01/b2
        if (tid < 128) {
            long ng = tile * 128 + tid;
            int cn = ng < N ? (int)ng : N - 1;
            float i0 = (float)g_ind0[cn];
            float i1 = (float)g_ind1[cn];
            const float* r = &red[tid * 12];
            float sv[4], sf[4], al[4];
            #pragma unroll
            for (int h = 0; h < 4; h++) {
                sv[h] = r[h]; sf[h] = r[4 + h]; al[h] = r[8 + h];
            }
            float bta[3][4];
            #pragma unroll
            for (int jr = 0; jr < 3; jr++) {
                float x[4];
                #pragma unroll
                for (int h = 0; h < 4; h++) {
                    float ar = (jr == 0) ? i0 * sv[h] : (jr == 1) ? i1 * sv[h] : sf[h];
                    float xx = al[h] + ar;
                    x[h] = (xx > 0.f) ? xx : 0.2f * xx;
                }
                float mx = fmaxf(fmaxf(x[0], x[1]), fmaxf(x[2], x[3]));
                float e0 = __expf(x[0] - mx), e1 = __expf(x[1] - mx);
                float e2 = __expf(x[2] - mx), e3 = __expf(x[3] - mx);
                float inv = 1.f / (e0 + e1 + e2 + e3);
                bta[jr][0] = e0 * inv; bta[jr][1] = e1 * inv;
                bta[jr][2] = e2 * inv; bta[jr][3] = e3 * inv;
            }
            #pragma unroll
            for (int h = 0; h < 4; h++) {
                gbuf[tid * 9 + h]     = bta[0][h] * i0 + bta[1][h] * i1;
                gbuf[tid * 9 + 4 + h] = bta[2][h];
            }
        }
        __syncthreads();

        // ---- output: relu(g01*(v+br) + b2*feat)
        switch (wg) {
            case 0: final_phase<0, 5>(acc, AHI, ALO, gbuf, br_s, out, tile, N, lane, mp); break;
            case 1: final_phase<5, 5>(acc, AHI, ALO, gbuf, br_s, out, tile, N, lane, mp); break;
            case 2: final_phase<10, 4>(acc, AHI, ALO, gbuf, br_s, out, tile, N, lane, mp); break;
            default: final_phase<14, 4>(acc, AHI, ALO, gbuf, br_s, out, tile, N, lane, mp); break;
        }
        // loop-top sync protects frags/red/gbuf
    }
}

extern "C" void kernel_launch(void* const* d_in, const int* in_sizes, int n_in,
                              void* d_out, int out_size) {
    // Inputs: feat, Wl, bl, Wr, br, attn_l, attn_r, rel_attn_l, rel_attn_r,
    //         alpha, src0, dst0, src1, dst1
    const float* feat = (const float*)d_in[0];
    const float* Wr   = (const float*)d_in[3];
    const float* br   = (const float*)d_in[4];
    const float* rl   = (const float*)d_in[7];
    const float* rr   = (const float*)d_in[8];
    const int* dst0   = (const int*)d_in[11];
    const int* dst1   = (const int*)d_in[13];
    float* out        = (float*)d_out;

    const int N  = in_sizes[0] / 128;
    const int E0 = in_sizes[11];
    const int E1 = in_sizes[13];

    const int SMEM_BYTES = SMEM_U32 * 4;
    cudaFuncSetAttribute(fused_kernel,
                         cudaFuncAttributeMaxDynamicSharedMemorySize, SMEM_BYTES);
    int nsm = 148;
    cudaDeviceGetAttribute(&nsm, cudaDevAttrMultiProcessorCount, 0);
    int T = (N + 127) >> 7;
    int grid = nsm < T ? nsm : T;
    fused_kernel<<<grid, 512, SMEM_BYTES>>>(feat, Wr, br, rl, rr,
                                            dst0, E0, dst1, E1, out, N);
}

// round 5
// speedup vs baseline: 2.6180x; 1.1238x over previous
#include <cuda_runtime.h>
#include <cuda_bf16.h>
#include <cstdint>

#define MAXN 100096

__device__ unsigned char g_ind0[MAXN];
__device__ unsigned char g_ind1[MAXN];
__device__ volatile unsigned int g_bar;

__device__ __forceinline__ void mma16816(float* c, const unsigned* a, const unsigned* b) {
    asm volatile(
        "mma.sync.aligned.m16n8k16.row.col.f32.bf16.bf16.f32 "
        "{%0,%1,%2,%3},{%4,%5,%6,%7},{%8,%9},{%0,%1,%2,%3};\n"
        : "+f"(c[0]), "+f"(c[1]), "+f"(c[2]), "+f"(c[3])
        : "r"(a[0]), "r"(a[1]), "r"(a[2]), "r"(a[3]), "r"(b[0]), "r"(b[1]));
}

__device__ __forceinline__ float bfl(unsigned u) {
    return __bfloat162float(__ushort_as_bfloat16((unsigned short)(u & 0xffffu)));
}
__device__ __forceinline__ float bfh(unsigned u) {
    return __bfloat162float(__ushort_as_bfloat16((unsigned short)(u >> 16)));
}

// fp32 pair -> bf16 hi (truncate-style via +0x8000 rounding) + bf16 lo residual
__device__ __forceinline__ void split2(float2 f, unsigned& hi, unsigned& lo) {
    unsigned u0 = __float_as_uint(f.x) + 0x8000u;
    unsigned u1 = __float_as_uint(f.y) + 0x8000u;
    asm("prmt.b32 %0,%1,%2,0x7632;" : "=r"(hi) : "r"(u0), "r"(u1));
    float l0 = f.x - __uint_as_float(u0 & 0xffff0000u);
    float l1 = f.y - __uint_as_float(u1 & 0xffff0000u);
    asm("cvt.rn.bf16x2.f32 %0, %1, %2;" : "=r"(lo) : "f"(l1), "f"(l0));
}

// Software grid barrier: grid <= #SMs, 1 block/SM -> all co-resident.
__device__ __forceinline__ void grid_bar(unsigned nb) {
    __syncthreads();
    if (threadIdx.x == 0) {
        __threadfence();
        unsigned old = atomicAdd((unsigned*)&g_bar, 1u);
        unsigned target = (old / nb + 1u) * nb;
        while (g_bar < target) { }
        __threadfence();
    }
    __syncthreads();
}

// smem layout (u32 units). STG pitch = 136 floats (8-word skew -> <=2-way banks)
#define PITCH     136
#define STG_OFF   0            // 17408 : fp32 feat staging, 128 rows x 136
#define AHI_OFF   17408        // 8192  : A hi frags, uint4 granule = (m,kc,ln)
#define ALO_OFF   25600        // 8192
#define BHI_OFF   33792        // 9216  : B-ext hi frags (18 n-tiles x 8 kc x 32 x uint2)
#define BLO_OFF   43008        // 9216
#define RED_OFF   52224        // 1536 floats : per-node sv[4] (+ch), sf[4], al[4]
#define GBUF_OFF  53760        // 1152 floats : per-node g01[4], b2[4] (pitch 9)
#define BRS_OFF   54912        // 128
#define QS_OFF    55040        // 512
#define CHS_OFF   55552        // 8
#define SMEM_U32  55560        // 222240 bytes

__device__ __forceinline__ void prefetch_tile(float* STG, const float* feat,
                                              long tile, int N, int tid) {
    #pragma unroll
    for (int it = 0; it < 8; it++) {
        int idx4 = tid + it * 512;
        int n = idx4 >> 5, c4 = idx4 & 31;
        long node = tile * 128 + n;
        if (node > N - 1) node = N - 1;
        const float4* src = ((const float4*)feat) + node * 32 + c4;
        unsigned dst = (unsigned)__cvta_generic_to_shared(&STG[n * PITCH + c4 * 4]);
        asm volatile("cp.async.cg.shared.global [%0],[%1],16;" :: "r"(dst), "l"(src));
    }
}

// fp32 staging -> bf16 hi/lo fragments. One thread builds one full uint4
// granule -> STS.128 conflict-free; reads are float2 with <=2-way conflicts.
__device__ __forceinline__ void convert_tile(const float* STG, int tid,
                                             unsigned* AHI, unsigned* ALO) {
    #pragma unroll
    for (int it = 0; it < 4; it++) {
        int u = tid + it * 512;
        int ln = u & 31, kc = (u >> 5) & 7, m = u >> 8;
        int n0 = m * 16 + (ln >> 2);
        int kA = kc * 16 + (ln & 3) * 2;
        const float* s0 = &STG[n0 * PITCH];
        const float* s1 = &STG[(n0 + 8) * PITCH];
        float2 a = *(const float2*)&s0[kA];
        float2 b = *(const float2*)&s1[kA];
        float2 c = *(const float2*)&s0[kA + 8];
        float2 d = *(const float2*)&s1[kA + 8];
        uint4 H, L;
        split2(a, H.x, L.x);
        split2(b, H.y, L.y);
        split2(c, H.z, L.z);
        split2(d, H.w, L.w);
        ((uint4*)AHI)[u] = H;
        ((uint4*)ALO)[u] = L;
    }
}

// One persistent kernel: flag zero/mark phases (grid barriers), then fused
// GEMM + beta-softmax + epilogue over 128-node tiles.
// Warp mapping: m = warp&7 (one 16-row m-tile), half = warp>>3.
// Each warp: 9 n-tiles (half*8 + 0..7 outputs, 16+half extras) -> balanced.
__global__ void __launch_bounds__(512, 1) fused_kernel(
    const float* __restrict__ feat, const float* __restrict__ Wr,
    const float* __restrict__ br, const float* __restrict__ rl,
    const float* __restrict__ rr,
    const int* __restrict__ d0, int E0, const int* __restrict__ d1, int E1,
    float* __restrict__ out, int N)
{
    extern __shared__ unsigned smem_u[];
    float*    STG = (float*)(smem_u + STG_OFF);
    unsigned* AHI = smem_u + AHI_OFF;
    unsigned* ALO = smem_u + ALO_OFF;
    unsigned* BHI = smem_u + BHI_OFF;
    unsigned* BLO = smem_u + BLO_OFF;
    float* red  = (float*)(smem_u + RED_OFF);
    float* gbuf = (float*)(smem_u + GBUF_OFF);
    float* br_s = (float*)(smem_u + BRS_OFF);
    float* q_s  = (float*)(smem_u + QS_OFF);
    float* ch_s = (float*)(smem_u + CHS_OFF);

    const int tid  = threadIdx.x;
    const int lane = tid & 31;
    const int warp = tid >> 5;
    const int m    = warp & 7;
    const int half = warp >> 3;
    const unsigned nb = gridDim.x;

    // ---- phase 0: zero flags
    for (int i = blockIdx.x * 512 + tid; i < MAXN / 4; i += nb * 512) {
        ((unsigned*)g_ind0)[i] = 0u;
        ((unsigned*)g_ind1)[i] = 0u;
    }
    grid_bar(nb);

    // ---- phase 1: mark flags
    for (int i = blockIdx.x * 512 + tid; i < E0 + E1; i += nb * 512) {
        if (i < E0) g_ind0[d0[i]] = 1;
        else        g_ind1[d1[i - E0]] = 1;
    }

    // ---- prologue (overlaps other blocks' marking)
    if (tid < 128) br_s[tid] = br[tid];
    __syncthreads();
    for (int p = tid; p < 512; p += 512) {
        int h = p >> 7, k = p & 127;
        float s = 0.f;
        #pragma unroll 4
        for (int t = 0; t < 32; t++)
            s += __ldg(&Wr[(h * 32 + t) * 128 + k]) * __ldg(&rr[h * 32 + t]);
        q_s[p] = s;
    }
    if (tid < 4) {
        float s = 0.f;
        for (int t = 0; t < 32; t++)
            s += __ldg(&br[tid * 32 + t]) * __ldg(&rr[tid * 32 + t]);
        ch_s[tid] = s;
    }
    __syncthreads();

    // B-ext fragments: t'<128 Wr; 128-131 q_h; 132-135 rr head-masked;
    // 136-139 rl head-masked; 140-143 zero. Stored in mma fragment layout.
    for (int i = tid; i < 9216; i += 512) {
        int j  = i & 1;
        int ln = (i >> 1) & 31;
        int kc = (i >> 6) & 7;
        int nt = i >> 9;
        int tp = nt * 8 + (ln >> 2);
        int k0 = kc * 16 + (ln & 3) * 2 + j * 8;
        float v[2];
        #pragma unroll
        for (int e = 0; e < 2; e++) {
            int k = k0 + e;
            float x;
            if (tp < 128)      x = __ldg(&Wr[tp * 128 + k]);
            else if (tp < 132) x = q_s[(tp - 128) * 128 + k];
            else if (tp < 136) x = ((k >> 5) == (tp - 132)) ? __ldg(&rr[k]) : 0.f;
            else if (tp < 140) x = ((k >> 5) == (tp - 136)) ? __ldg(&rl[k]) : 0.f;
            else               x = 0.f;
            v[e] = x;
        }
        unsigned hi, lo;
        split2(make_float2(v[0], v[1]), hi, lo);
        BHI[i] = hi;
        BLO[i] = lo;
    }

    grid_bar(nb);   // marking done everywhere; prologue visible

    // ---- main loop over node tiles
    const int T = (N + 127) >> 7;
    long tile0 = blockIdx.x;
    if (tile0 < T) prefetch_tile(STG, feat, tile0, N, tid);
    asm volatile("cp.async.commit_group;");

    for (long tile = tile0; tile < T; tile += nb) {
        asm volatile("cp.async.wait_group 0;");
        __syncthreads();   // STG ready; prev-iter final done with frags

        convert_tile(STG, tid, AHI, ALO);
        __syncthreads();   // frags ready; STG consumed

        long nxt = tile + nb;
        if (nxt < T) prefetch_tile(STG, feat, nxt, N, tid);
        asm volatile("cp.async.commit_group;");

        // ---- MMA: 1 m-tile x 9 n-tiles per warp, 3-term bf16 split
        float acc[9][4];
        #pragma unroll
        for (int i = 0; i < 9; i++)
            #pragma unroll
            for (int c = 0; c < 4; c++) acc[i][c] = 0.f;

        #pragma unroll 1
        for (int kc = 0; kc < 8; kc++) {
            uint4 ah = ((const uint4*)AHI)[(m * 8 + kc) * 32 + lane];
            uint4 al = ((const uint4*)ALO)[(m * 8 + kc) * 32 + lane];
            #pragma unroll
            for (int i = 0; i < 9; i++) {
                int gnt = (i < 8) ? half * 8 + i : 16 + half;
                uint2 bh = ((const uint2*)BHI)[(gnt * 8 + kc) * 32 + lane];
                uint2 bl = ((const uint2*)BLO)[(gnt * 8 + kc) * 32 + lane];
                mma16816(acc[i], (const unsigned*)&ah, (const unsigned*)&bh);
                mma16816(acc[i], (const unsigned*)&ah, (const unsigned*)&bl);
                mma16816(acc[i], (const unsigned*)&al, (const unsigned*)&bh);
            }
        }

        // ---- extras: half0 -> gnt16 (sv cols 0-3 + ch, sf cols 4-7),
        //              half1 -> gnt17 (al cols 0-3; cols 4-7 are zero pad)
        {
            int cidx = (lane & 3) * 2;
            #pragma unroll
            for (int j0 = 0; j0 < 2; j0++) {
                int nl = m * 16 + (lane >> 2) + 8 * j0;
                float s0 = acc[8][2 * j0];
                float s1 = acc[8][2 * j0 + 1];
                if (half == 0) {
                    if (cidx < 4) { s0 += ch_s[cidx]; s1 += ch_s[cidx + 1]; }
                    red[nl * 12 + cidx]     = s0;   // sv (cidx<4) / sf (cidx>=4)
                    red[nl * 12 + cidx + 1] = s1;
                } else if (cidx < 4) {
                    red[nl * 12 + 8 + cidx]     = s0;   // al
                    red[nl * 12 + 8 + cidx + 1] = s1;
                }
            }
        }
        __syncthreads();

        // ---- beta softmax over heads; fold flags into g01/b2
        if (tid < 128) {
            long ng = tile * 128 + tid;
            int cn = ng < N ? (int)ng : N - 1;
            float i0 = (float)g_ind0[cn];
            float i1 = (float)g_ind1[cn];
            const float* r = &red[tid * 12];
            float sv[4], sf[4], al[4];
            #pragma unroll
            for (int h = 0; h < 4; h++) {
                sv[h] = r[h]; sf[h] = r[4 + h]; al[h] = r[8 + h];
            }
            float bta[3][4];
            #pragma unroll
            for (int jr = 0; jr < 3; jr++) {
                float x[4];
                #pragma unroll
                for (int h = 0; h < 4; h++) {
                    float ar = (jr == 0) ? i0 * sv[h] : (jr == 1) ? i1 * sv[h] : sf[h];
                    float xx = al[h] + ar;
                    x[h] = (xx > 0.f) ? xx : 0.2f * xx;
                }
                float mx = fmaxf(fmaxf(x[0], x[1]), fmaxf(x[2], x[3]));
                float e0 = __expf(x[0] - mx), e1 = __expf(x[1] - mx);
                float e2 = __expf(x[2] - mx), e3 = __expf(x[3] - mx);
                float inv = 1.f / (e0 + e1 + e2 + e3);
                bta[jr][0] = e0 * inv; bta[jr][1] = e1 * inv;
                bta[jr][2] = e2 * inv; bta[jr][3] = e3 * inv;
            }
            #pragma unroll
            for (int h = 0; h < 4; h++) {
                gbuf[tid * 9 + h]     = bta[0][h] * i0 + bta[1][h] * i1;
                gbuf[tid * 9 + 4 + h] = bta[2][h];
            }
        }
        __syncthreads();

        // ---- output: relu(g01*(v+br) + b2*feat); feat via one LDS.128 per
        // A-frag granule (contains exactly this thread's rows/cols)
        #pragma unroll
        for (int ip = 0; ip < 4; ip++) {
            int kca = half * 4 + ip;
            uint4 fh4 = ((const uint4*)AHI)[(m * 8 + kca) * 32 + lane];
            uint4 fl4 = ((const uint4*)ALO)[(m * 8 + kca) * 32 + lane];
            const unsigned* fh = (const unsigned*)&fh4;
            const unsigned* fl = (const unsigned*)&fl4;
            #pragma unroll
            for (int iodd = 0; iodd < 2; iodd++) {
                int i = 2 * ip + iodd;
                int gnt = half * 8 + i;
                int head = gnt >> 2;
                int tcol = gnt * 8 + (lane & 3) * 2;
                float2 brv = *(const float2*)&br_s[tcol];
                #pragma unroll
                for (int j0 = 0; j0 < 2; j0++) {
                    int nl = m * 16 + (lane >> 2) + 8 * j0;
                    long ng = tile * 128 + nl;
                    if (ng < N) {
                        int j = j0 + 2 * iodd;
                        float f0 = bfl(fh[j]) + bfl(fl[j]);
                        float f1 = bfh(fh[j]) + bfh(fl[j]);
                        float g01 = gbuf[nl * 9 + head];
                        float b2v = gbuf[nl * 9 + 4 + head];
                        float v0 = acc[i][2 * j0]     + brv.x;
                        float v1 = acc[i][2 * j0 + 1] + brv.y;
                        float o0 = fmaxf(fmaf(g01, v0, b2v * f0), 0.f);
                        float o1 = fmaxf(fmaf(g01, v1, b2v * f1), 0.f);
                        *(float2*)&out[ng * 128 + tcol] = make_float2(o0, o1);
                    }
                }
            }
        }
        // loop-top sync protects frags/red/gbuf
    }
}

extern "C" void kernel_launch(void* const* d_in, const int* in_sizes, int n_in,
                              void* d_out, int out_size) {
    // Inputs: feat, Wl, bl, Wr, br, attn_l, attn_r, rel_attn_l, rel_attn_r,
    //         alpha, src0, dst0, src1, dst1
    const float* feat = (const float*)d_in[0];
    const float* Wr   = (const float*)d_in[3];
    const float* br   = (const float*)d_in[4];
    const float* rl   = (const float*)d_in[7];
    const float* rr   = (const float*)d_in[8];
    const int* dst0   = (const int*)d_in[11];
    const int* dst1   = (const int*)d_in[13];
    float* out        = (float*)d_out;

    const int N  = in_sizes[0] / 128;
    const int E0 = in_sizes[11];
    const int E1 = in_sizes[13];

    const int SMEM_BYTES = SMEM_U32 * 4;
    cudaFuncSetAttribute(fused_kernel,
                         cudaFuncAttributeMaxDynamicSharedMemorySize, SMEM_BYTES);
    int nsm = 148;
    cudaDeviceGetAttribute(&nsm, cudaDevAttrMultiProcessorCount, 0);
    int T = (N + 127) >> 7;
    int grid = nsm < T ? nsm : T;
    fused_kernel<<<grid, 512, SMEM_BYTES>>>(feat, Wr, br, rl, rr,
                                            dst0, E0, dst1, E1, out, N);
}